// round 15
// baseline (speedup 1.0000x reference)
#include <cuda_runtime.h>
#include <cstdint>
#include <math.h>
#include <mma.h>

using namespace nvcuda;

// Problem constants
#define B_ 2
#define S_ 2048
#define D_ 2048
#define H_ 16
#define HD_ 128
#define RD_ 64
#define L_ 512
#define QDIM (HD_ + RD_)      // 192
#define KVDIM (2*HD_ + RD_)   // 320
#define MROWS (B_ * S_)       // 4096

// Scratch (device globals; no cudaMalloc allowed)
__device__ float g_ckv[MROWS * L_];
__device__ float g_cq [MROWS * L_];
__device__ float g_kv [MROWS * H_ * KVDIM];
__device__ float g_q  [MROWS * H_ * QDIM];
__device__ float g_ctx[MROWS * H_ * HD_];
// tf32-rounded operand copies
__device__ float g_xt [MROWS * D_];
__device__ float g_w1t[D_ * L_];
__device__ float g_w2t[L_ * H_ * KVDIM];
__device__ float g_w3t[D_ * L_];
__device__ float g_w4t[L_ * H_ * QDIM];
__device__ float g_w5t[H_ * HD_ * D_];

// ----------------------------------------------------------------------------
// Elementwise fp32 -> tf32-valued fp32 (RN), vectorized  (R8 exact)
// ----------------------------------------------------------------------------
__global__ void __launch_bounds__(256) cvt_tf32_kernel(
    const float4* __restrict__ in, float4* __restrict__ out, int n4)
{
    int i = blockIdx.x * blockDim.x + threadIdx.x;
    if (i < n4) {
        float4 v = in[i];
        v.x = wmma::__float_to_tf32(v.x);
        v.y = wmma::__float_to_tf32(v.y);
        v.z = wmma::__float_to_tf32(v.z);
        v.w = wmma::__float_to_tf32(v.w);
        out[i] = v;
    }
}

// ----------------------------------------------------------------------------
// cp.async helpers
// ----------------------------------------------------------------------------
__device__ __forceinline__ void cp16(float* dst, const float* src) {
    unsigned int s = (unsigned int)__cvta_generic_to_shared(dst);
    asm volatile("cp.async.cg.shared.global [%0], [%1], 16;\n" :: "r"(s), "l"(src));
}
#define CP_COMMIT() asm volatile("cp.async.commit_group;\n" ::: "memory")
#define CP_WAIT1()  asm volatile("cp.async.wait_group 1;\n" ::: "memory")

// ----------------------------------------------------------------------------
// TF32 tensor-core GEMM, 3-stage cp.async pipeline, operands pre-rounded.
// NEW: 128x256 block tile, BK=32, 256 threads = 8 warps (2x4), warp tile 64x64.
// Per-warp MMA structure identical to R8 (16 MMAs / 8 frag loads per ks-step);
// fills, barriers, and pipeline turns per FLOP are halved.
// ----------------------------------------------------------------------------
#define AP 36
#define BP 260
#define STAGES 3
#define A_STG (128 * AP)
#define B_STG (32 * BP)
#define GEMM_SMEM (STAGES * (A_STG + B_STG) * (int)sizeof(float))

__global__ void __launch_bounds__(256, 1) tgemm_kernel(
    const float* __restrict__ A, const float* __restrict__ Bm,
    float* __restrict__ C, int M, int N, int K, int roundC)
{
    extern __shared__ float sm_g[];
    float* As = sm_g;
    float* Bs = sm_g + STAGES * A_STG;

    const int tid  = threadIdx.x;
    const int bRow = blockIdx.y * 128;
    const int bCol = blockIdx.x * 256;
    const int w    = tid >> 5;
    const int wm   = w & 1;      // 0..1 -> 64 rows
    const int wn   = w >> 1;     // 0..3 -> 64 cols of 256

    wmma::fragment<wmma::accumulator, 16, 16, 8, float> c[4][4];
#pragma unroll
    for (int i = 0; i < 4; i++)
#pragma unroll
        for (int j = 0; j < 4; j++) wmma::fill_fragment(c[i][j], 0.f);

    const int ktiles = K >> 5;

    // fill: A 128x32 (1024 float4) + B 32x256 (2048 float4) = 3072 tasks
    auto load_tile = [&](int buf, int kt) {
        float* as = As + buf * A_STG;
        float* bs = Bs + buf * B_STG;
        const float* Ag = A + (size_t)bRow * K + kt * 32;
        const float* Bg = Bm + (size_t)(kt * 32) * N + bCol;
#pragma unroll
        for (int p = 0; p < 12; p++) {
            int idx = p * 256 + tid;
            if (idx < 1024) {
                int r  = idx >> 3, c4 = idx & 7;
                cp16(&as[r * AP + c4 * 4], Ag + (size_t)r * K + c4 * 4);
            } else {
                int j  = idx - 1024;
                int rb = j >> 6, cb4 = j & 63;
                cp16(&bs[rb * BP + cb4 * 4], Bg + (size_t)rb * N + cb4 * 4);
            }
        }
    };

    load_tile(0, 0); CP_COMMIT();
    load_tile(1, 1); CP_COMMIT();

    for (int i = 0; i < ktiles; i++) {
        CP_WAIT1();
        __syncthreads();
        if (i + 2 < ktiles) load_tile((i + 2) % STAGES, i + 2);
        CP_COMMIT();

        const float* as = As + (i % STAGES) * A_STG;
        const float* bs = Bs + (i % STAGES) * B_STG;
#pragma unroll
        for (int ks = 0; ks < 32; ks += 8) {
            wmma::fragment<wmma::matrix_a, 16, 16, 8, wmma::precision::tf32, wmma::row_major> a[4];
            wmma::fragment<wmma::matrix_b, 16, 16, 8, wmma::precision::tf32, wmma::row_major> b[4];
#pragma unroll
            for (int ii = 0; ii < 4; ii++)
                wmma::load_matrix_sync(a[ii], &as[(wm * 64 + ii * 16) * AP + ks], AP);
#pragma unroll
            for (int j = 0; j < 4; j++)
                wmma::load_matrix_sync(b[j], &bs[ks * BP + wn * 64 + j * 16], BP);
#pragma unroll
            for (int ii = 0; ii < 4; ii++)
#pragma unroll
                for (int j = 0; j < 4; j++)
                    wmma::mma_sync(c[ii][j], a[ii], b[j], c[ii][j]);
        }
    }

    if (roundC) {
#pragma unroll
        for (int i = 0; i < 4; i++)
#pragma unroll
            for (int j = 0; j < 4; j++)
#pragma unroll
                for (int t = 0; t < c[i][j].num_elements; t++)
                    c[i][j].x[t] = wmma::__float_to_tf32(c[i][j].x[t]);
    }

#pragma unroll
    for (int i = 0; i < 4; i++)
#pragma unroll
        for (int j = 0; j < 4; j++) {
            size_t row = bRow + wm * 64 + i * 16;
            size_t col = bCol + wn * 64 + j * 16;
            wmma::store_matrix_sync(C + row * N + col, c[i][j], N, wmma::mem_row_major);
        }
}

// ----------------------------------------------------------------------------
// RoPE (in place)  (R8 exact)
// ----------------------------------------------------------------------------
__global__ void __launch_bounds__(512) rope_kernel()
{
    const int bs  = blockIdx.x;
    const int s   = bs % S_;
    const int tid = threadIdx.x;
    const int h   = tid >> 5;
    const int i   = tid & 31;

    const float inv_freq = __expf(-(float)i * (9.210340371976184f / 32.0f));
    const float freq = (float)s * inv_freq;
    const float c  = cosf(freq);
    const float sn = sinf(freq);

    {
        size_t base = ((size_t)bs * H_ + h) * QDIM + HD_;
        float x1 = g_q[base + i];
        float x2 = g_q[base + i + 32];
        g_q[base + i]      = x1 * c - x2 * sn;
        g_q[base + i + 32] = x2 * c + x1 * sn;
    }
    {
        size_t base = ((size_t)bs * H_ + h) * KVDIM + HD_;
        float x1 = g_kv[base + i];
        float x2 = g_kv[base + i + 32];
        g_kv[base + i]      = x1 * c - x2 * sn;
        g_kv[base + i + 32] = x2 * c + x1 * sn;
    }
}

// ----------------------------------------------------------------------------
// Causal flash attention (R8 exact: fp32 register-tiled 4x8, scalar fills,
// serial __expf softmax, tf32-rounded ctx store).
// ----------------------------------------------------------------------------
#define TQ 64
#define TK 64
#define QP 68
#define VP 132
#define SP 68
#define ATTN_SMEM ((192*QP + 32*QP + TK*VP + TQ*SP + 192) * (int)sizeof(float))

__global__ void __launch_bounds__(256) attn_kernel()
{
    extern __shared__ float sm[];
    float* sQt  = sm;
    float* sKt  = sQt + 192 * QP;
    float* sV   = sKt + 32 * QP;
    float* sS   = sV  + TK * VP;
    float* mRow = sS  + TQ * SP;
    float* lRow = mRow + 64;
    float* aRow = lRow + 64;

    const int qt  = blockIdx.x;
    const int h   = blockIdx.y;
    const int b   = blockIdx.z;
    const int qs  = qt * TQ;
    const int tid = threadIdx.x;
    const int ty  = tid >> 4;
    const int tx  = tid & 15;
    const int r0  = ty * 4;

    for (int idx = tid; idx < TQ * QDIM; idx += 256) {
        int r = idx / QDIM, k = idx % QDIM;
        sQt[k * QP + r] = g_q[((size_t)(b * S_ + qs + r) * H_ + h) * QDIM + k];
    }
    if (tid < TQ) { mRow[tid] = -INFINITY; lRow[tid] = 0.f; }

    float acc[4][8];
#pragma unroll
    for (int i = 0; i < 4; i++)
#pragma unroll
        for (int j = 0; j < 8; j++) acc[i][j] = 0.f;

    const float scale = 0.07216878364870323f;

    for (int kt = 0; kt <= qt; kt++) {
        const int ks = kt * TK;
        __syncthreads();

        for (int idx4 = tid; idx4 < TK * (HD_ / 4); idx4 += 256) {
            int c = idx4 >> 5, j4 = idx4 & 31;
            float4 v = *(const float4*)(g_kv + ((size_t)(b * S_ + ks + c) * H_ + h) * KVDIM + QDIM + j4 * 4);
            *(float4*)&sV[c * VP + j4 * 4] = v;
        }

        float s[4][4];
#pragma unroll
        for (int i = 0; i < 4; i++)
#pragma unroll
            for (int j = 0; j < 4; j++) s[i][j] = 0.f;

        for (int dc = 0; dc < 6; dc++) {
            if (dc > 0) __syncthreads();
            {
                int c = tid >> 5;
                int d = tid & 31;
#pragma unroll
                for (int rr = 0; rr < 8; rr++) {
                    int kc = c + rr * 8;
                    sKt[d * QP + kc] = g_kv[((size_t)(b * S_ + ks + kc) * H_ + h) * KVDIM + dc * 32 + d];
                }
            }
            __syncthreads();
#pragma unroll
            for (int k = 0; k < 32; k++) {
                const int kk = dc * 32 + k;
                float4 qa = *(const float4*)&sQt[kk * QP + r0];
                float4 kb = *(const float4*)&sKt[k  * QP + tx * 4];
                float ra[4] = {qa.x, qa.y, qa.z, qa.w};
                float rb[4] = {kb.x, kb.y, kb.z, kb.w};
#pragma unroll
                for (int i = 0; i < 4; i++)
#pragma unroll
                    for (int j = 0; j < 4; j++)
                        s[i][j] += ra[i] * rb[j];
            }
        }

        {
            const bool diag = (kt == qt);
#pragma unroll
            for (int i = 0; i < 4; i++) {
                const int gr = qs + r0 + i;
                float4 w;
                float* ws = &w.x;
#pragma unroll
                for (int j = 0; j < 4; j++) {
                    int kc = ks + tx * 4 + j;
                    ws[j] = (diag && kc > gr) ? -1e30f : s[i][j] * scale;
                }
                *(float4*)&sS[(r0 + i) * SP + tx * 4] = w;
            }
        }
        __syncthreads();

        if (tid < TQ) {
            const int r = tid;
            float mold = mRow[r];
            float mx = mold;
#pragma unroll
            for (int c = 0; c < TK; c++) mx = fmaxf(mx, sS[r * SP + c]);
            float a = __expf(mold - mx);
            float sum = 0.f;
#pragma unroll
            for (int c = 0; c < TK; c++) {
                float p = __expf(sS[r * SP + c] - mx);
                sS[r * SP + c] = p;
                sum += p;
            }
            lRow[r] = lRow[r] * a + sum;
            mRow[r] = mx;
            aRow[r] = a;
        }
        __syncthreads();

        {
            float al[4];
#pragma unroll
            for (int i = 0; i < 4; i++) al[i] = aRow[r0 + i];
#pragma unroll
            for (int i = 0; i < 4; i++)
#pragma unroll
                for (int j = 0; j < 8; j++) acc[i][j] *= al[i];

#pragma unroll 4
            for (int c = 0; c < TK; c++) {
                float4 v0 = *(const float4*)&sV[c * VP + tx * 8];
                float4 v1 = *(const float4*)&sV[c * VP + tx * 8 + 4];
                float p[4];
#pragma unroll
                for (int i = 0; i < 4; i++) p[i] = sS[(r0 + i) * SP + c];
#pragma unroll
                for (int i = 0; i < 4; i++) {
                    acc[i][0] += p[i] * v0.x;
                    acc[i][1] += p[i] * v0.y;
                    acc[i][2] += p[i] * v0.z;
                    acc[i][3] += p[i] * v0.w;
                    acc[i][4] += p[i] * v1.x;
                    acc[i][5] += p[i] * v1.y;
                    acc[i][6] += p[i] * v1.z;
                    acc[i][7] += p[i] * v1.w;
                }
            }
        }
    }

#pragma unroll
    for (int i = 0; i < 4; i++) {
        const float invl = 1.0f / lRow[r0 + i];
        size_t ob = ((size_t)(b * S_ + qs + r0 + i) * H_ + h) * HD_ + tx * 8;
        float o[8];
#pragma unroll
        for (int j = 0; j < 8; j++) o[j] = wmma::__float_to_tf32(acc[i][j] * invl);
        *(float4*)(g_ctx + ob)     = make_float4(o[0], o[1], o[2], o[3]);
        *(float4*)(g_ctx + ob + 4) = make_float4(o[4], o[5], o[6], o[7]);
    }
}

// ----------------------------------------------------------------------------
// Launch. Order keeps deps but puts the down-GEMM at app-launch index 3
// (ncu capture slot) so the current GEMM finally gets profiled.
// Inputs (metadata order): x, mask, w_kv_down, w_kv_up, w_q_down, w_q_up, w_o
// ----------------------------------------------------------------------------
extern "C" void kernel_launch(void* const* d_in, const int* in_sizes, int n_in,
                              void* d_out, int out_size)
{
    (void)in_sizes; (void)n_in; (void)out_size;
    const float* x         = (const float*)d_in[0];
    const float* w_kv_down = (const float*)d_in[2];
    const float* w_kv_up   = (const float*)d_in[3];
    const float* w_q_down  = (const float*)d_in[4];
    const float* w_q_up    = (const float*)d_in[5];
    const float* w_o       = (const float*)d_in[6];
    float* out = (float*)d_out;

    float *ckv, *cq, *kv, *q, *ctx, *xt, *w1t, *w2t, *w3t, *w4t, *w5t;
    cudaGetSymbolAddress((void**)&ckv, g_ckv);
    cudaGetSymbolAddress((void**)&cq,  g_cq);
    cudaGetSymbolAddress((void**)&kv,  g_kv);
    cudaGetSymbolAddress((void**)&q,   g_q);
    cudaGetSymbolAddress((void**)&ctx, g_ctx);
    cudaGetSymbolAddress((void**)&xt,  g_xt);
    cudaGetSymbolAddress((void**)&w1t, g_w1t);
    cudaGetSymbolAddress((void**)&w2t, g_w2t);
    cudaGetSymbolAddress((void**)&w3t, g_w3t);
    cudaGetSymbolAddress((void**)&w4t, g_w4t);
    cudaGetSymbolAddress((void**)&w5t, g_w5t);

    cudaFuncSetAttribute(tgemm_kernel, cudaFuncAttributeMaxDynamicSharedMemorySize, GEMM_SMEM);
    cudaFuncSetAttribute(attn_kernel,  cudaFuncAttributeMaxDynamicSharedMemorySize, ATTN_SMEM);

    auto cvt = [&](const float* src, float* dst, int n) {
        int n4 = n >> 2;
        cvt_tf32_kernel<<<(n4 + 255) / 256, 256>>>((const float4*)src, (float4*)dst, n4);
    };

    dim3 blk(256);
    // 0-2: conversions needed by the down GEMMs
    cvt(x,         xt,  MROWS * D_);
    cvt(w_kv_down, w1t, D_ * L_);
    cvt(w_q_down,  w3t, D_ * L_);
    // 3: down projection ckv — ncu capture slot (N=512 -> 2 col tiles)
    tgemm_kernel<<<dim3(L_/256, MROWS/128), blk, GEMM_SMEM>>>(xt, w1t, ckv, MROWS, L_, D_, 1);
    // 4: down projection cq
    tgemm_kernel<<<dim3(L_/256, MROWS/128), blk, GEMM_SMEM>>>(xt, w3t, cq,  MROWS, L_, D_, 1);
    // 5-6: up-projection weight conversions
    cvt(w_kv_up,   w2t, L_ * H_ * KVDIM);
    cvt(w_q_up,    w4t, L_ * H_ * QDIM);
    // 7-8: up projections
    tgemm_kernel<<<dim3((H_*KVDIM)/256, MROWS/128), blk, GEMM_SMEM>>>(ckv, w2t, kv, MROWS, H_*KVDIM, L_, 0);
    tgemm_kernel<<<dim3((H_*QDIM)/256,  MROWS/128), blk, GEMM_SMEM>>>(cq,  w4t, q,  MROWS, H_*QDIM,  L_, 0);
    // 9: rope
    rope_kernel<<<MROWS, 512>>>();
    // 10: attention (R8 exact)
    attn_kernel<<<dim3(S_/TQ, H_, B_), 256, ATTN_SMEM>>>();
    // 11: output weight conversion
    cvt(w_o, w5t, H_ * HD_ * D_);
    // 12: output projection
    tgemm_kernel<<<dim3(D_/256, MROWS/128), blk, GEMM_SMEM>>>(ctx, w5t, out, MROWS, D_, D_, 0);
}

// round 16
// speedup vs baseline: 1.1233x; 1.1233x over previous
#include <cuda_runtime.h>
#include <cstdint>
#include <math.h>
#include <mma.h>

using namespace nvcuda;

// Problem constants
#define B_ 2
#define S_ 2048
#define D_ 2048
#define H_ 16
#define HD_ 128
#define RD_ 64
#define L_ 512
#define QDIM (HD_ + RD_)      // 192
#define KVDIM (2*HD_ + RD_)   // 320
#define MROWS (B_ * S_)       // 4096

// Scratch (device globals; no cudaMalloc allowed)
__device__ float g_ckv[MROWS * L_];
__device__ float g_cq [MROWS * L_];
__device__ float g_kv [MROWS * H_ * KVDIM];
__device__ float g_q  [MROWS * H_ * QDIM];
__device__ float g_ctx[MROWS * H_ * HD_];
// tf32-rounded operand copies
__device__ float g_xt [MROWS * D_];
__device__ float g_w1t[D_ * L_];
__device__ float g_w2t[L_ * H_ * KVDIM];
__device__ float g_w3t[D_ * L_];
__device__ float g_w4t[L_ * H_ * QDIM];
__device__ float g_w5t[H_ * HD_ * D_];

// ----------------------------------------------------------------------------
// Elementwise fp32 -> tf32-valued fp32 (RN), vectorized  (R8 exact)
// ----------------------------------------------------------------------------
__global__ void __launch_bounds__(256) cvt_tf32_kernel(
    const float4* __restrict__ in, float4* __restrict__ out, int n4)
{
    int i = blockIdx.x * blockDim.x + threadIdx.x;
    if (i < n4) {
        float4 v = in[i];
        v.x = wmma::__float_to_tf32(v.x);
        v.y = wmma::__float_to_tf32(v.y);
        v.z = wmma::__float_to_tf32(v.z);
        v.w = wmma::__float_to_tf32(v.w);
        out[i] = v;
    }
}

// ----------------------------------------------------------------------------
// cp.async helpers
// ----------------------------------------------------------------------------
__device__ __forceinline__ void cp16(float* dst, const float* src) {
    unsigned int s = (unsigned int)__cvta_generic_to_shared(dst);
    asm volatile("cp.async.cg.shared.global [%0], [%1], 16;\n" :: "r"(s), "l"(src));
}
#define CP_COMMIT() asm volatile("cp.async.commit_group;\n" ::: "memory")
#define CP_WAIT1()  asm volatile("cp.async.wait_group 1;\n" ::: "memory")

// ----------------------------------------------------------------------------
// TF32 tensor-core GEMM body (R8 exact: 128x128 tile, BK=32, 128 threads =
// 4 warps 2x2, 64x64 warp tile, 3-stage cp.async, 2 CTAs/SM).
// ----------------------------------------------------------------------------
#define AP 36
#define BP 132
#define STAGES 3
#define A_STG (128 * AP)
#define B_STG (32 * BP)
#define GEMM_SMEM (STAGES * (A_STG + B_STG) * (int)sizeof(float))

__device__ __forceinline__ void tgemm_body(
    const float* __restrict__ A, const float* __restrict__ Bm,
    float* __restrict__ C, int N, int K, int roundC, int bRow, int bCol)
{
    extern __shared__ float sm_g[];
    float* As = sm_g;
    float* Bs = sm_g + STAGES * A_STG;

    const int tid = threadIdx.x;
    const int w   = tid >> 5;
    const int wm  = w & 1;
    const int wn  = w >> 1;

    wmma::fragment<wmma::accumulator, 16, 16, 8, float> c[4][4];
#pragma unroll
    for (int i = 0; i < 4; i++)
#pragma unroll
        for (int j = 0; j < 4; j++) wmma::fill_fragment(c[i][j], 0.f);

    const int ktiles = K >> 5;

    auto load_tile = [&](int buf, int kt) {
        float* as = As + buf * A_STG;
        float* bs = Bs + buf * B_STG;
        const float* Ag = A + (size_t)bRow * K + kt * 32;
        const float* Bg = Bm + (size_t)(kt * 32) * N + bCol;
#pragma unroll
        for (int p = 0; p < 8; p++) {
            int idx = p * 128 + tid;
            int r  = idx >> 3, c4  = idx & 7;
            cp16(&as[r * AP + c4 * 4], Ag + (size_t)r * K + c4 * 4);
            int rb = idx >> 5, cb4 = idx & 31;
            cp16(&bs[rb * BP + cb4 * 4], Bg + (size_t)rb * N + cb4 * 4);
        }
    };

    load_tile(0, 0); CP_COMMIT();
    load_tile(1, 1); CP_COMMIT();

    for (int i = 0; i < ktiles; i++) {
        CP_WAIT1();
        __syncthreads();
        if (i + 2 < ktiles) load_tile((i + 2) % STAGES, i + 2);
        CP_COMMIT();

        const float* as = As + (i % STAGES) * A_STG;
        const float* bs = Bs + (i % STAGES) * B_STG;
#pragma unroll
        for (int ks = 0; ks < 32; ks += 8) {
            wmma::fragment<wmma::matrix_a, 16, 16, 8, wmma::precision::tf32, wmma::row_major> a[4];
            wmma::fragment<wmma::matrix_b, 16, 16, 8, wmma::precision::tf32, wmma::row_major> b[4];
#pragma unroll
            for (int ii = 0; ii < 4; ii++)
                wmma::load_matrix_sync(a[ii], &as[(wm * 64 + ii * 16) * AP + ks], AP);
#pragma unroll
            for (int j = 0; j < 4; j++)
                wmma::load_matrix_sync(b[j], &bs[ks * BP + wn * 64 + j * 16], BP);
#pragma unroll
            for (int ii = 0; ii < 4; ii++)
#pragma unroll
                for (int j = 0; j < 4; j++)
                    wmma::mma_sync(c[ii][j], a[ii], b[j], c[ii][j]);
        }
    }

    if (roundC) {
#pragma unroll
        for (int i = 0; i < 4; i++)
#pragma unroll
            for (int j = 0; j < 4; j++)
#pragma unroll
                for (int t = 0; t < c[i][j].num_elements; t++)
                    c[i][j].x[t] = wmma::__float_to_tf32(c[i][j].x[t]);
    }

#pragma unroll
    for (int i = 0; i < 4; i++)
#pragma unroll
        for (int j = 0; j < 4; j++) {
            size_t row = bRow + wm * 64 + i * 16;
            size_t col = bCol + wn * 64 + j * 16;
            wmma::store_matrix_sync(C + row * N + col, c[i][j], N, wmma::mem_row_major);
        }
}

// Fused down projections: one launch fills the 2-CTA/SM slots
// (two separate 128-CTA launches leave half the chip idle).
__global__ void __launch_bounds__(128, 2) gemm_down_kernel()
{
    int bx = blockIdx.x;
    if (bx < 4) tgemm_body(g_xt, g_w1t, g_ckv, L_, D_, 1, blockIdx.y * 128, bx * 128);
    else        tgemm_body(g_xt, g_w3t, g_cq,  L_, D_, 1, blockIdx.y * 128, (bx - 4) * 128);
}

// Fused up projections: merges two ragged wave-tails into one.
__global__ void __launch_bounds__(128, 2) gemm_up_kernel()
{
    int bx = blockIdx.x;
    if (bx < 40) tgemm_body(g_ckv, g_w2t, g_kv, H_ * KVDIM, L_, 0, blockIdx.y * 128, bx * 128);
    else         tgemm_body(g_cq,  g_w4t, g_q,  H_ * QDIM,  L_, 0, blockIdx.y * 128, (bx - 40) * 128);
}

__global__ void __launch_bounds__(128, 2) gemm_out_kernel(float* __restrict__ out)
{
    tgemm_body(g_ctx, g_w5t, out, D_, D_, 0, blockIdx.y * 128, blockIdx.x * 128);
}

// ----------------------------------------------------------------------------
// RoPE (in place)  (R8 exact)
// ----------------------------------------------------------------------------
__global__ void __launch_bounds__(512) rope_kernel()
{
    const int bs  = blockIdx.x;
    const int s   = bs % S_;
    const int tid = threadIdx.x;
    const int h   = tid >> 5;
    const int i   = tid & 31;

    const float inv_freq = __expf(-(float)i * (9.210340371976184f / 32.0f));
    const float freq = (float)s * inv_freq;
    const float c  = cosf(freq);
    const float sn = sinf(freq);

    {
        size_t base = ((size_t)bs * H_ + h) * QDIM + HD_;
        float x1 = g_q[base + i];
        float x2 = g_q[base + i + 32];
        g_q[base + i]      = x1 * c - x2 * sn;
        g_q[base + i + 32] = x2 * c + x1 * sn;
    }
    {
        size_t base = ((size_t)bs * H_ + h) * KVDIM + HD_;
        float x1 = g_kv[base + i];
        float x2 = g_kv[base + i + 32];
        g_kv[base + i]      = x1 * c - x2 * sn;
        g_kv[base + i + 32] = x2 * c + x1 * sn;
    }
}

// ----------------------------------------------------------------------------
// Causal flash attention (R8 exact).
// ----------------------------------------------------------------------------
#define TQ 64
#define TK 64
#define QP 68
#define VP 132
#define SP 68
#define ATTN_SMEM ((192*QP + 32*QP + TK*VP + TQ*SP + 192) * (int)sizeof(float))

__global__ void __launch_bounds__(256) attn_kernel()
{
    extern __shared__ float sm[];
    float* sQt  = sm;
    float* sKt  = sQt + 192 * QP;
    float* sV   = sKt + 32 * QP;
    float* sS   = sV  + TK * VP;
    float* mRow = sS  + TQ * SP;
    float* lRow = mRow + 64;
    float* aRow = lRow + 64;

    const int qt  = blockIdx.x;
    const int h   = blockIdx.y;
    const int b   = blockIdx.z;
    const int qs  = qt * TQ;
    const int tid = threadIdx.x;
    const int ty  = tid >> 4;
    const int tx  = tid & 15;
    const int r0  = ty * 4;

    for (int idx = tid; idx < TQ * QDIM; idx += 256) {
        int r = idx / QDIM, k = idx % QDIM;
        sQt[k * QP + r] = g_q[((size_t)(b * S_ + qs + r) * H_ + h) * QDIM + k];
    }
    if (tid < TQ) { mRow[tid] = -INFINITY; lRow[tid] = 0.f; }

    float acc[4][8];
#pragma unroll
    for (int i = 0; i < 4; i++)
#pragma unroll
        for (int j = 0; j < 8; j++) acc[i][j] = 0.f;

    const float scale = 0.07216878364870323f;

    for (int kt = 0; kt <= qt; kt++) {
        const int ks = kt * TK;
        __syncthreads();

        for (int idx4 = tid; idx4 < TK * (HD_ / 4); idx4 += 256) {
            int c = idx4 >> 5, j4 = idx4 & 31;
            float4 v = *(const float4*)(g_kv + ((size_t)(b * S_ + ks + c) * H_ + h) * KVDIM + QDIM + j4 * 4);
            *(float4*)&sV[c * VP + j4 * 4] = v;
        }

        float s[4][4];
#pragma unroll
        for (int i = 0; i < 4; i++)
#pragma unroll
            for (int j = 0; j < 4; j++) s[i][j] = 0.f;

        for (int dc = 0; dc < 6; dc++) {
            if (dc > 0) __syncthreads();
            {
                int c = tid >> 5;
                int d = tid & 31;
#pragma unroll
                for (int rr = 0; rr < 8; rr++) {
                    int kc = c + rr * 8;
                    sKt[d * QP + kc] = g_kv[((size_t)(b * S_ + ks + kc) * H_ + h) * KVDIM + dc * 32 + d];
                }
            }
            __syncthreads();
#pragma unroll
            for (int k = 0; k < 32; k++) {
                const int kk = dc * 32 + k;
                float4 qa = *(const float4*)&sQt[kk * QP + r0];
                float4 kb = *(const float4*)&sKt[k  * QP + tx * 4];
                float ra[4] = {qa.x, qa.y, qa.z, qa.w};
                float rb[4] = {kb.x, kb.y, kb.z, kb.w};
#pragma unroll
                for (int i = 0; i < 4; i++)
#pragma unroll
                    for (int j = 0; j < 4; j++)
                        s[i][j] += ra[i] * rb[j];
            }
        }

        {
            const bool diag = (kt == qt);
#pragma unroll
            for (int i = 0; i < 4; i++) {
                const int gr = qs + r0 + i;
                float4 w;
                float* ws = &w.x;
#pragma unroll
                for (int j = 0; j < 4; j++) {
                    int kc = ks + tx * 4 + j;
                    ws[j] = (diag && kc > gr) ? -1e30f : s[i][j] * scale;
                }
                *(float4*)&sS[(r0 + i) * SP + tx * 4] = w;
            }
        }
        __syncthreads();

        if (tid < TQ) {
            const int r = tid;
            float mold = mRow[r];
            float mx = mold;
#pragma unroll
            for (int c = 0; c < TK; c++) mx = fmaxf(mx, sS[r * SP + c]);
            float a = __expf(mold - mx);
            float sum = 0.f;
#pragma unroll
            for (int c = 0; c < TK; c++) {
                float p = __expf(sS[r * SP + c] - mx);
                sS[r * SP + c] = p;
                sum += p;
            }
            lRow[r] = lRow[r] * a + sum;
            mRow[r] = mx;
            aRow[r] = a;
        }
        __syncthreads();

        {
            float al[4];
#pragma unroll
            for (int i = 0; i < 4; i++) al[i] = aRow[r0 + i];
#pragma unroll
            for (int i = 0; i < 4; i++)
#pragma unroll
                for (int j = 0; j < 8; j++) acc[i][j] *= al[i];

#pragma unroll 4
            for (int c = 0; c < TK; c++) {
                float4 v0 = *(const float4*)&sV[c * VP + tx * 8];
                float4 v1 = *(const float4*)&sV[c * VP + tx * 8 + 4];
                float p[4];
#pragma unroll
                for (int i = 0; i < 4; i++) p[i] = sS[(r0 + i) * SP + c];
#pragma unroll
                for (int i = 0; i < 4; i++) {
                    acc[i][0] += p[i] * v0.x;
                    acc[i][1] += p[i] * v0.y;
                    acc[i][2] += p[i] * v0.z;
                    acc[i][3] += p[i] * v0.w;
                    acc[i][4] += p[i] * v1.x;
                    acc[i][5] += p[i] * v1.y;
                    acc[i][6] += p[i] * v1.z;
                    acc[i][7] += p[i] * v1.w;
                }
            }
        }
    }

#pragma unroll
    for (int i = 0; i < 4; i++) {
        const float invl = 1.0f / lRow[r0 + i];
        size_t ob = ((size_t)(b * S_ + qs + r0 + i) * H_ + h) * HD_ + tx * 8;
        float o[8];
#pragma unroll
        for (int j = 0; j < 8; j++) o[j] = wmma::__float_to_tf32(acc[i][j] * invl);
        *(float4*)(g_ctx + ob)     = make_float4(o[0], o[1], o[2], o[3]);
        *(float4*)(g_ctx + ob + 4) = make_float4(o[4], o[5], o[6], o[7]);
    }
}

// ----------------------------------------------------------------------------
// Launch. Fused down GEMM at app-launch index 3 (ncu capture slot).
// Inputs (metadata order): x, mask, w_kv_down, w_kv_up, w_q_down, w_q_up, w_o
// ----------------------------------------------------------------------------
extern "C" void kernel_launch(void* const* d_in, const int* in_sizes, int n_in,
                              void* d_out, int out_size)
{
    (void)in_sizes; (void)n_in; (void)out_size;
    const float* x         = (const float*)d_in[0];
    const float* w_kv_down = (const float*)d_in[2];
    const float* w_kv_up   = (const float*)d_in[3];
    const float* w_q_down  = (const float*)d_in[4];
    const float* w_q_up    = (const float*)d_in[5];
    const float* w_o       = (const float*)d_in[6];
    float* out = (float*)d_out;

    float *xt, *w1t, *w2t, *w3t, *w4t, *w5t;
    cudaGetSymbolAddress((void**)&xt,  g_xt);
    cudaGetSymbolAddress((void**)&w1t, g_w1t);
    cudaGetSymbolAddress((void**)&w2t, g_w2t);
    cudaGetSymbolAddress((void**)&w3t, g_w3t);
    cudaGetSymbolAddress((void**)&w4t, g_w4t);
    cudaGetSymbolAddress((void**)&w5t, g_w5t);

    cudaFuncSetAttribute(gemm_down_kernel, cudaFuncAttributeMaxDynamicSharedMemorySize, GEMM_SMEM);
    cudaFuncSetAttribute(gemm_up_kernel,   cudaFuncAttributeMaxDynamicSharedMemorySize, GEMM_SMEM);
    cudaFuncSetAttribute(gemm_out_kernel,  cudaFuncAttributeMaxDynamicSharedMemorySize, GEMM_SMEM);
    cudaFuncSetAttribute(attn_kernel,      cudaFuncAttributeMaxDynamicSharedMemorySize, ATTN_SMEM);

    auto cvt = [&](const float* src, float* dst, int n) {
        int n4 = n >> 2;
        cvt_tf32_kernel<<<(n4 + 255) / 256, 256>>>((const float4*)src, (float4*)dst, n4);
    };

    // 0-2: conversions needed by the fused down GEMM
    cvt(x,         xt,  MROWS * D_);
    cvt(w_kv_down, w1t, D_ * L_);
    cvt(w_q_down,  w3t, D_ * L_);
    // 3: fused down projections — ncu capture slot (256 CTAs, fills 2/SM slots)
    gemm_down_kernel<<<dim3(8, 32), 128, GEMM_SMEM>>>();
    // 4-5: up-projection weight conversions
    cvt(w_kv_up, w2t, L_ * H_ * KVDIM);
    cvt(w_q_up,  w4t, L_ * H_ * QDIM);
    // 6: fused up projections (2048 CTAs, single merged tail)
    gemm_up_kernel<<<dim3(64, 32), 128, GEMM_SMEM>>>();
    // 7: rope
    rope_kernel<<<MROWS, 512>>>();
    // 8: attention (R8 exact)
    attn_kernel<<<dim3(S_/TQ, H_, B_), 256, ATTN_SMEM>>>();
    // 9: output weight conversion
    cvt(w_o, w5t, H_ * HD_ * D_);
    // 10: output projection
    gemm_out_kernel<<<dim3(16, 32), 128, GEMM_SMEM>>>(out);
}